// round 9
// baseline (speedup 1.0000x reference)
#include <cuda_runtime.h>

#define BB 4
#define CC 64
#define HH 256
#define WW 256
#define HW (HH*WW)
#define CHW (CC*HW)

#define NSPLIT 8
#define ECH (CC/NSPLIT)   // 8 channels per edge block
#define SB 4              // channels staged per barrier pair in edge kernel

#define TILE 16           // output rows per fused-blur block
#define HBROWS (TILE+6)   // 22 hblur rows incl. halo
#define FB_CH 4           // channels per fused-blur block

#define SIGMA_MIN 0.6f
#define SIGMA_MAX 1.2f

// Scratch (static device allocations — no cudaMalloc allowed)
__device__ float d_edge[BB*HW];                  // 1 MB
__device__ float d_edge_part[NSPLIT][BB*HW];     // 8 MB partial channel-sums
__device__ float d_g[4][BB*HW];                  // 4 MB (symmetric taps)
__device__ unsigned int d_minmax[2*BB];          // per-batch {min,max} uint bits

__global__ void init_minmax_kernel() {
    int i = threadIdx.x;
    if (i < BB) {
        d_minmax[2*i]   = 0x7f800000u; // +inf
        d_minmax[2*i+1] = 0u;          // 0
    }
}

// Partial Sobel edge-energy sums over 8 channels per block.
// Block (64,4): 8-row x 256-col tile; 4 channels staged per barrier pair.
__global__ __launch_bounds__(256) void edge_partial_kernel(const float* __restrict__ x) {
    __shared__ float xs[SB][10][264];

    const int tx = threadIdx.x;
    const int ty = threadIdx.y;
    const int tid = ty*64 + tx;
    const int h0 = blockIdx.x*8;
    const int sp = blockIdx.y;
    const int b  = blockIdx.z;

    if (tid < SB*10) {
        int ch = tid / 10, r = tid % 10;
        xs[ch][r][3] = 0.f; xs[ch][r][260] = 0.f;
    }

    const float* xb = x + (size_t)b*CHW + (size_t)sp*ECH*HW;
    float acc[2][4] = {};

    for (int cb = 0; cb < ECH; cb += SB) {
        __syncthreads();
        #pragma unroll
        for (int k = 0; k < 10; k++) {
            int i  = tid + k*256;
            int ch = i / 640;
            int rm = i - ch*640;
            int r  = rm >> 6, q = rm & 63;
            int gh = h0 - 1 + r;
            float4 v = make_float4(0.f, 0.f, 0.f, 0.f);
            if (gh >= 0 && gh < HH)
                v = *(const float4*)(xb + (size_t)(cb + ch)*HW + gh*WW + q*4);
            *(float4*)&xs[ch][r][4 + q*4] = v;
        }
        __syncthreads();

        #pragma unroll
        for (int ch = 0; ch < SB; ch++) {
            #pragma unroll
            for (int rr = 0; rr < 2; rr++) {
                const int base = ty + rr*4;
                float d[3][4], s[3][4];
                #pragma unroll
                for (int r = 0; r < 3; r++) {
                    const float* row = &xs[ch][base + r][4 + 4*tx];
                    float  l = row[-1];
                    float4 m = *(const float4*)row;
                    float rt = row[4];
                    d[r][0] = m.y - l;    s[r][0] = l   + 2.f*m.x + m.y;
                    d[r][1] = m.z - m.x;  s[r][1] = m.x + 2.f*m.y + m.z;
                    d[r][2] = m.w - m.y;  s[r][2] = m.y + 2.f*m.z + m.w;
                    d[r][3] = rt  - m.z;  s[r][3] = m.z + 2.f*m.w + rt;
                }
                #pragma unroll
                for (int j = 0; j < 4; j++) {
                    float gx = d[0][j] + 2.f*d[1][j] + d[2][j];
                    float gy = s[2][j] - s[0][j];
                    acc[rr][j] = fmaf(gx, gx, acc[rr][j]);
                    acc[rr][j] = fmaf(gy, gy, acc[rr][j]);
                }
            }
        }
    }

    #pragma unroll
    for (int rr = 0; rr < 2; rr++) {
        const int h = h0 + ty + rr*4;
        float4 e = make_float4(acc[rr][0], acc[rr][1], acc[rr][2], acc[rr][3]);
        *(float4*)(d_edge_part[sp] + b*HW + h*WW + 4*tx) = e;
    }
}

// Sum partials -> edge; per-batch min/max via block reduce + uint atomics.
__global__ __launch_bounds__(256) void edge_reduce_kernel() {
    __shared__ float smin[8], smax[8];
    const int idx4 = blockIdx.x*256 + threadIdx.x;
    const int b = idx4 >> 14;

    float4 s = make_float4(0.f, 0.f, 0.f, 0.f);
    #pragma unroll
    for (int sp = 0; sp < NSPLIT; sp++) {
        float4 v = *(const float4*)(d_edge_part[sp] + (size_t)idx4*4);
        s.x += v.x; s.y += v.y; s.z += v.z; s.w += v.w;
    }
    s.x *= (1.f/64.f); s.y *= (1.f/64.f); s.z *= (1.f/64.f); s.w *= (1.f/64.f);
    *(float4*)(d_edge + (size_t)idx4*4) = s;

    float vmin = fminf(fminf(s.x, s.y), fminf(s.z, s.w));
    float vmax = fmaxf(fmaxf(s.x, s.y), fmaxf(s.z, s.w));
    #pragma unroll
    for (int o = 16; o; o >>= 1) {
        vmin = fminf(vmin, __shfl_xor_sync(0xffffffffu, vmin, o));
        vmax = fmaxf(vmax, __shfl_xor_sync(0xffffffffu, vmax, o));
    }
    const int wid = threadIdx.x >> 5, lane = threadIdx.x & 31;
    if (lane == 0) { smin[wid] = vmin; smax[wid] = vmax; }
    __syncthreads();
    if (threadIdx.x == 0) {
        float m = smin[0], M = smax[0];
        #pragma unroll
        for (int i = 1; i < 8; i++) { m = fminf(m, smin[i]); M = fmaxf(M, smax[i]); }
        atomicMin(&d_minmax[2*b],   __float_as_uint(m));
        atomicMax(&d_minmax[2*b+1], __float_as_uint(M));
    }
}

// Per-pixel normalized Gaussian taps. 1 expf per pixel; scalar = max parallelism.
__global__ __launch_bounds__(256) void gauss_kernel() {
    const int idx = blockIdx.x*256 + threadIdx.x;
    const int b = idx >> 16;   // HW per batch
    const float emin = __uint_as_float(d_minmax[2*b]);
    const float rden = __fdividef(1.f, __uint_as_float(d_minmax[2*b+1]) + 1e-6f);

    float e = (d_edge[idx] - emin) * rden;
    float s = SIGMA_MIN + (SIGMA_MAX - SIGMA_MIN)*e;
    float t = __fdividef(1.f, s);
    float inv = 0.5f*t*t;
    float w2 = __expf(-inv);
    float w2_2 = w2*w2;
    float w1 = w2_2*w2_2;
    float w0 = w1*w1*w2;
    float r = __fdividef(1.f, 2.f*(w0 + w1 + w2) + 1.f);
    d_g[0][idx] = w0*r;
    d_g[1][idx] = w1*r;
    d_g[2][idx] = w2*r;
    d_g[3][idx] = r;
}

// Fused H+V blur. Block (64,4): 16 output rows x 256 cols x 4 channels.
// hblur 22 rows -> smem; vblur -> out. Per-thread g for its 4 rows in regs
// (shared between both passes); halo-row g staged once in smem.
__global__ __launch_bounds__(256, 2) void fblur_kernel(const float* __restrict__ x,
                                                       float* __restrict__ out) {
    __shared__ float hb[HBROWS][260];       // hblur results (quad-aligned rows)
    __shared__ float hg[4][6][256];         // g for 6 halo rows (local 0,1,2,19,20,21)

    const int tx = threadIdx.x;             // 0..63
    const int ty = threadIdx.y;             // 0..3
    const int tid = ty*64 + tx;
    const int h0 = blockIdx.x*TILE;
    const int c0 = blockIdx.y*FB_CH;
    const int b  = blockIdx.z;
    const int w4 = tx*4;
    const float4 z4 = make_float4(0.f, 0.f, 0.f, 0.f);

    // stage halo g (channel-invariant): 4 planes x 6 rows x 64 quads = 1536 tasks
    #pragma unroll
    for (int k = 0; k < 6; k++) {
        int i = tid + k*256;
        int plane = i / 384;
        int rem = i - plane*384;
        int r6 = rem >> 6, q = rem & 63;
        int gh = (r6 < 3) ? (h0 - 3 + r6) : (h0 + TILE + r6 - 3);
        float4 v = z4;
        if (gh >= 0 && gh < HH)
            v = *(const float4*)&d_g[plane][b*HW + gh*WW + q*4];
        *(float4*)&hg[plane][r6][q*4] = v;
    }

    // per-thread g for its 4 rows (global rows h0+4ty+j) — used by BOTH passes
    float4 G0[4], G1[4], G2[4], G3[4];
    #pragma unroll
    for (int j = 0; j < 4; j++) {
        const int gi = b*HW + (h0 + 4*ty + j)*WW + w4;
        G0[j] = *(const float4*)&d_g[0][gi];
        G1[j] = *(const float4*)&d_g[1][gi];
        G2[j] = *(const float4*)&d_g[2][gi];
        G3[j] = *(const float4*)&d_g[3][gi];
    }
    __syncthreads();

    const bool hasL = (tx > 0), hasR = (tx < 63);
    const bool haloT = (ty == 0), haloB = (ty == 3);

    for (int c = 0; c < FB_CH; c++) {
        const float* xc = x + (size_t)b*CHW + (size_t)(c0 + c)*HW;

        // hblur: own 4 rows (local hb rows 4ty+3..4ty+6, global h0+4ty+j)
        #pragma unroll
        for (int j = 0; j < 4; j++) {
            const int gh = h0 + 4*ty + j;
            const float* p = xc + gh*WW + w4;
            float4 m  = *(const float4*)p;
            float4 lf = hasL ? *(const float4*)(p - 4) : z4;
            float4 rf = hasR ? *(const float4*)(p + 4) : z4;
            float v0=lf.y, v1=lf.z, v2=lf.w, v3=m.x, v4=m.y, v5=m.z, v6=m.w, v7=rf.x, v8=rf.y, v9=rf.z;
            float4 o;
            o.x = fmaf(G0[j].x, v0+v6, fmaf(G1[j].x, v1+v5, fmaf(G2[j].x, v2+v4, G3[j].x*v3)));
            o.y = fmaf(G0[j].y, v1+v7, fmaf(G1[j].y, v2+v6, fmaf(G2[j].y, v3+v5, G3[j].y*v4)));
            o.z = fmaf(G0[j].z, v2+v8, fmaf(G1[j].z, v3+v7, fmaf(G2[j].z, v4+v6, G3[j].z*v5)));
            o.w = fmaf(G0[j].w, v3+v9, fmaf(G1[j].w, v4+v8, fmaf(G2[j].w, v5+v7, G3[j].w*v6)));
            *(float4*)&hb[4*ty + 3 + j][w4] = o;
        }

        // hblur: halo rows (ty0 -> local 0,1,2; ty3 -> local 19,20,21)
        if (haloT || haloB) {
            #pragma unroll
            for (int k = 0; k < 3; k++) {
                const int r6 = haloT ? k : 3 + k;
                const int r  = haloT ? k : TILE + 3 + k;
                const int gh = h0 - 3 + r;
                float4 o = z4;
                if (gh >= 0 && gh < HH) {
                    float4 g0 = *(const float4*)&hg[0][r6][w4];
                    float4 g1 = *(const float4*)&hg[1][r6][w4];
                    float4 g2 = *(const float4*)&hg[2][r6][w4];
                    float4 g3 = *(const float4*)&hg[3][r6][w4];
                    const float* p = xc + gh*WW + w4;
                    float4 m  = *(const float4*)p;
                    float4 lf = hasL ? *(const float4*)(p - 4) : z4;
                    float4 rf = hasR ? *(const float4*)(p + 4) : z4;
                    float v0=lf.y, v1=lf.z, v2=lf.w, v3=m.x, v4=m.y, v5=m.z, v6=m.w, v7=rf.x, v8=rf.y, v9=rf.z;
                    o.x = fmaf(g0.x, v0+v6, fmaf(g1.x, v1+v5, fmaf(g2.x, v2+v4, g3.x*v3)));
                    o.y = fmaf(g0.y, v1+v7, fmaf(g1.y, v2+v6, fmaf(g2.y, v3+v5, g3.y*v4)));
                    o.z = fmaf(g0.z, v2+v8, fmaf(g1.z, v3+v7, fmaf(g2.z, v4+v6, g3.z*v5)));
                    o.w = fmaf(g0.w, v3+v9, fmaf(g1.w, v4+v8, fmaf(g2.w, v5+v7, g3.w*v6)));
                }
                *(float4*)&hb[r][w4] = o;
            }
        }
        __syncthreads();

        // vblur: 10-row window covers the thread's 4 outputs
        float4 wn[10];
        #pragma unroll
        for (int i = 0; i < 10; i++)
            wn[i] = *(const float4*)&hb[4*ty + i][w4];

        float* oc = out + (size_t)b*CHW + (size_t)(c0 + c)*HW + w4;
        #pragma unroll
        for (int j = 0; j < 4; j++) {
            float4 o;
            o.x = fmaf(G0[j].x, wn[j].x+wn[j+6].x, fmaf(G1[j].x, wn[j+1].x+wn[j+5].x, fmaf(G2[j].x, wn[j+2].x+wn[j+4].x, G3[j].x*wn[j+3].x)));
            o.y = fmaf(G0[j].y, wn[j].y+wn[j+6].y, fmaf(G1[j].y, wn[j+1].y+wn[j+5].y, fmaf(G2[j].y, wn[j+2].y+wn[j+4].y, G3[j].y*wn[j+3].y)));
            o.z = fmaf(G0[j].z, wn[j].z+wn[j+6].z, fmaf(G1[j].z, wn[j+1].z+wn[j+5].z, fmaf(G2[j].z, wn[j+2].z+wn[j+4].z, G3[j].z*wn[j+3].z)));
            o.w = fmaf(G0[j].w, wn[j].w+wn[j+6].w, fmaf(G1[j].w, wn[j+1].w+wn[j+5].w, fmaf(G2[j].w, wn[j+2].w+wn[j+4].w, G3[j].w*wn[j+3].w)));
            *(float4*)(oc + (h0 + 4*ty + j)*WW) = o;
        }
        __syncthreads();
    }
}

extern "C" void kernel_launch(void* const* d_in, const int* in_sizes, int n_in,
                              void* d_out, int out_size) {
    const float* x = (const float*)d_in[0];
    float* out = (float*)d_out;

    init_minmax_kernel<<<1, 32>>>();

    edge_partial_kernel<<<dim3(HH/8, NSPLIT, BB), dim3(64, 4)>>>(x);

    edge_reduce_kernel<<<(BB*HW/4)/256, 256>>>();

    gauss_kernel<<<(BB*HW)/256, 256>>>();

    fblur_kernel<<<dim3(HH/TILE, CC/FB_CH, BB), dim3(64, 4)>>>(x, out);
}

// round 11
// speedup vs baseline: 1.0162x; 1.0162x over previous
#include <cuda_runtime.h>
#include <cuda_fp16.h>

#define BB 4
#define CC 64
#define HH 256
#define WW 256
#define HW (HH*WW)
#define CHW (CC*HW)

#define NSPLIT 8
#define ECH (CC/NSPLIT)   // 8 channels per edge block
#define SB 4              // channels staged per barrier pair in edge kernel
#define BCH 8             // channels per blur block

#define SIGMA_MIN 0.6f
#define SIGMA_MAX 1.2f

// Scratch (static device allocations — no cudaMalloc allowed)
__device__ float d_edge[BB*HW];                  // 1 MB
__device__ float d_edge_part[NSPLIT][BB*HW];     // 8 MB partial channel-sums
__device__ float d_g[4][BB*HW];                  // 4 MB (symmetric taps)
__device__ __half d_tmp[(size_t)BB*CHW];         // 32 MB horizontal-pass result (fp16)
__device__ unsigned int d_minmax[2*BB];          // per-batch {min,max} uint bits

__device__ __forceinline__ float4 ld_h4(const __half* p) {
    uint2 u = *(const uint2*)p;
    __half2 h0 = *(__half2*)&u.x;
    __half2 h1 = *(__half2*)&u.y;
    float2 a = __half22float2(h0), b = __half22float2(h1);
    return make_float4(a.x, a.y, b.x, b.y);
}

__device__ __forceinline__ void st_h4(__half* p, float4 v) {
    __half2 h0 = __floats2half2_rn(v.x, v.y);
    __half2 h1 = __floats2half2_rn(v.z, v.w);
    uint2 u;
    u.x = *(unsigned int*)&h0;
    u.y = *(unsigned int*)&h1;
    *(uint2*)p = u;
}

__global__ void init_minmax_kernel() {
    int i = threadIdx.x;
    if (i < BB) {
        d_minmax[2*i]   = 0x7f800000u; // +inf
        d_minmax[2*i+1] = 0u;          // 0
    }
}

// Partial Sobel edge-energy sums over 8 channels per block.
// Block (64,4): 8-row x 256-col tile; 4 channels staged per barrier pair.
__global__ __launch_bounds__(256) void edge_partial_kernel(const float* __restrict__ x) {
    __shared__ float xs[SB][10][264];

    const int tx = threadIdx.x;
    const int ty = threadIdx.y;
    const int tid = ty*64 + tx;
    const int h0 = blockIdx.x*8;
    const int sp = blockIdx.y;
    const int b  = blockIdx.z;

    if (tid < SB*10) {
        int ch = tid / 10, r = tid % 10;
        xs[ch][r][3] = 0.f; xs[ch][r][260] = 0.f;
    }

    const float* xb = x + (size_t)b*CHW + (size_t)sp*ECH*HW;
    float acc[2][4] = {};

    for (int cb = 0; cb < ECH; cb += SB) {
        __syncthreads();
        #pragma unroll
        for (int k = 0; k < 10; k++) {
            int i  = tid + k*256;
            int ch = i / 640;
            int rm = i - ch*640;
            int r  = rm >> 6, q = rm & 63;
            int gh = h0 - 1 + r;
            float4 v = make_float4(0.f, 0.f, 0.f, 0.f);
            if (gh >= 0 && gh < HH)
                v = *(const float4*)(xb + (size_t)(cb + ch)*HW + gh*WW + q*4);
            *(float4*)&xs[ch][r][4 + q*4] = v;
        }
        __syncthreads();

        #pragma unroll
        for (int ch = 0; ch < SB; ch++) {
            #pragma unroll
            for (int rr = 0; rr < 2; rr++) {
                const int base = ty + rr*4;
                float d[3][4], s[3][4];
                #pragma unroll
                for (int r = 0; r < 3; r++) {
                    const float* row = &xs[ch][base + r][4 + 4*tx];
                    float  l = row[-1];
                    float4 m = *(const float4*)row;
                    float rt = row[4];
                    d[r][0] = m.y - l;    s[r][0] = l   + 2.f*m.x + m.y;
                    d[r][1] = m.z - m.x;  s[r][1] = m.x + 2.f*m.y + m.z;
                    d[r][2] = m.w - m.y;  s[r][2] = m.y + 2.f*m.z + m.w;
                    d[r][3] = rt  - m.z;  s[r][3] = m.z + 2.f*m.w + rt;
                }
                #pragma unroll
                for (int j = 0; j < 4; j++) {
                    float gx = d[0][j] + 2.f*d[1][j] + d[2][j];
                    float gy = s[2][j] - s[0][j];
                    acc[rr][j] = fmaf(gx, gx, acc[rr][j]);
                    acc[rr][j] = fmaf(gy, gy, acc[rr][j]);
                }
            }
        }
    }

    #pragma unroll
    for (int rr = 0; rr < 2; rr++) {
        const int h = h0 + ty + rr*4;
        float4 e = make_float4(acc[rr][0], acc[rr][1], acc[rr][2], acc[rr][3]);
        *(float4*)(d_edge_part[sp] + b*HW + h*WW + 4*tx) = e;
    }
}

// Sum partials -> edge; per-batch min/max via block reduce + uint atomics.
__global__ __launch_bounds__(256) void edge_reduce_kernel() {
    __shared__ float smin[8], smax[8];
    const int idx4 = blockIdx.x*256 + threadIdx.x;
    const int b = idx4 >> 14;

    float4 s = make_float4(0.f, 0.f, 0.f, 0.f);
    #pragma unroll
    for (int sp = 0; sp < NSPLIT; sp++) {
        float4 v = *(const float4*)(d_edge_part[sp] + (size_t)idx4*4);
        s.x += v.x; s.y += v.y; s.z += v.z; s.w += v.w;
    }
    s.x *= (1.f/64.f); s.y *= (1.f/64.f); s.z *= (1.f/64.f); s.w *= (1.f/64.f);
    *(float4*)(d_edge + (size_t)idx4*4) = s;

    float vmin = fminf(fminf(s.x, s.y), fminf(s.z, s.w));
    float vmax = fmaxf(fmaxf(s.x, s.y), fmaxf(s.z, s.w));
    #pragma unroll
    for (int o = 16; o; o >>= 1) {
        vmin = fminf(vmin, __shfl_xor_sync(0xffffffffu, vmin, o));
        vmax = fmaxf(vmax, __shfl_xor_sync(0xffffffffu, vmax, o));
    }
    const int wid = threadIdx.x >> 5, lane = threadIdx.x & 31;
    if (lane == 0) { smin[wid] = vmin; smax[wid] = vmax; }
    __syncthreads();
    if (threadIdx.x == 0) {
        float m = smin[0], M = smax[0];
        #pragma unroll
        for (int i = 1; i < 8; i++) { m = fminf(m, smin[i]); M = fmaxf(M, smax[i]); }
        atomicMin(&d_minmax[2*b],   __float_as_uint(m));
        atomicMax(&d_minmax[2*b+1], __float_as_uint(M));
    }
}

// Per-pixel normalized Gaussian taps. 1 expf per pixel; scalar = max parallelism.
__global__ __launch_bounds__(256) void gauss_kernel() {
    const int idx = blockIdx.x*256 + threadIdx.x;
    const int b = idx >> 16;   // HW per batch
    const float emin = __uint_as_float(d_minmax[2*b]);
    const float rden = __fdividef(1.f, __uint_as_float(d_minmax[2*b+1]) + 1e-6f);

    float e = (d_edge[idx] - emin) * rden;
    float s = SIGMA_MIN + (SIGMA_MAX - SIGMA_MIN)*e;
    float t = __fdividef(1.f, s);
    float inv = 0.5f*t*t;
    float w2 = __expf(-inv);
    float w2_2 = w2*w2;
    float w1 = w2_2*w2_2;
    float w0 = w1*w1*w2;
    float r = __fdividef(1.f, 2.f*(w0 + w1 + w2) + 1.f);
    d_g[0][idx] = w0*r;
    d_g[1][idx] = w1*r;
    d_g[2][idx] = w2*r;
    d_g[3][idx] = r;
}

// Horizontal pass: thread = 4 outputs x 8 channels; g in regs; fp16 tmp store.
__global__ __launch_bounds__(256) void hblur_kernel(const float* __restrict__ x) {
    const int tx = threadIdx.x;                 // 0..63
    const int h  = blockIdx.x*4 + threadIdx.y;
    const int c0 = blockIdx.y*BCH;
    const int b  = blockIdx.z;
    const int w4 = tx*4;
    const int pidx = b*HW + h*WW + w4;

    const float4 G0 = *(const float4*)&d_g[0][pidx];
    const float4 G1 = *(const float4*)&d_g[1][pidx];
    const float4 G2 = *(const float4*)&d_g[2][pidx];
    const float4 G3 = *(const float4*)&d_g[3][pidx];

    const float* xr = x     + (size_t)b*CHW + (size_t)c0*HW + h*WW + w4;
    __half*      tr = d_tmp + (size_t)b*CHW + (size_t)c0*HW + h*WW + w4;
    const bool hasL = (tx > 0), hasR = (tx < 63);
    const float4 z4 = make_float4(0.f, 0.f, 0.f, 0.f);

    #pragma unroll 2
    for (int c = 0; c < BCH; c++) {
        const float* p = xr + (size_t)c*HW;
        float4 m  = *(const float4*)p;
        float4 lf = hasL ? *(const float4*)(p - 4) : z4;
        float4 rf = hasR ? *(const float4*)(p + 4) : z4;
        float v0=lf.y, v1=lf.z, v2=lf.w, v3=m.x, v4=m.y, v5=m.z, v6=m.w, v7=rf.x, v8=rf.y, v9=rf.z;
        float4 o;
        o.x = fmaf(G0.x, v0+v6, fmaf(G1.x, v1+v5, fmaf(G2.x, v2+v4, G3.x*v3)));
        o.y = fmaf(G0.y, v1+v7, fmaf(G1.y, v2+v6, fmaf(G2.y, v3+v5, G3.y*v4)));
        o.z = fmaf(G0.z, v2+v8, fmaf(G1.z, v3+v7, fmaf(G2.z, v4+v6, G3.z*v5)));
        o.w = fmaf(G0.w, v3+v9, fmaf(G1.w, v4+v8, fmaf(G2.w, v5+v7, G3.w*v6)));
        st_h4(tr + (size_t)c*HW, o);
    }
}

// Vertical pass: thread = 4 outputs x 8 channels; 7 guarded fp16 row loads.
__global__ __launch_bounds__(256) void vblur_kernel(float* __restrict__ out) {
    const int tx = threadIdx.x;
    const int h  = blockIdx.x*4 + threadIdx.y;
    const int c0 = blockIdx.y*BCH;
    const int b  = blockIdx.z;
    const int w4 = tx*4;
    const int pidx = b*HW + h*WW + w4;

    const float4 G0 = *(const float4*)&d_g[0][pidx];
    const float4 G1 = *(const float4*)&d_g[1][pidx];
    const float4 G2 = *(const float4*)&d_g[2][pidx];
    const float4 G3 = *(const float4*)&d_g[3][pidx];

    const __half* tp = d_tmp + (size_t)b*CHW + (size_t)c0*HW + h*WW + w4;
    float*        op = out   + (size_t)b*CHW + (size_t)c0*HW + h*WW + w4;

    const bool m1 = (h >= 1), m2 = (h >= 2), m3 = (h >= 3);
    const bool p1 = (h < HH-1), p2 = (h < HH-2), p3 = (h < HH-3);
    const float4 z4 = make_float4(0.f, 0.f, 0.f, 0.f);

    #pragma unroll 2
    for (int c = 0; c < BCH; c++) {
        const __half* p = tp + (size_t)c*HW;
        float4 cm = ld_h4(p);
        float4 u1 = m1 ? ld_h4(p -   WW) : z4;
        float4 d1 = p1 ? ld_h4(p +   WW) : z4;
        float4 u2 = m2 ? ld_h4(p - 2*WW) : z4;
        float4 d2 = p2 ? ld_h4(p + 2*WW) : z4;
        float4 u3 = m3 ? ld_h4(p - 3*WW) : z4;
        float4 d3 = p3 ? ld_h4(p + 3*WW) : z4;
        float4 o;
        o.x = fmaf(G0.x, u3.x+d3.x, fmaf(G1.x, u2.x+d2.x, fmaf(G2.x, u1.x+d1.x, G3.x*cm.x)));
        o.y = fmaf(G0.y, u3.y+d3.y, fmaf(G1.y, u2.y+d2.y, fmaf(G2.y, u1.y+d1.y, G3.y*cm.y)));
        o.z = fmaf(G0.z, u3.z+d3.z, fmaf(G1.z, u2.z+d2.z, fmaf(G2.z, u1.z+d1.z, G3.z*cm.z)));
        o.w = fmaf(G0.w, u3.w+d3.w, fmaf(G1.w, u2.w+d2.w, fmaf(G2.w, u1.w+d1.w, G3.w*cm.w)));
        *(float4*)(op + (size_t)c*HW) = o;
    }
}

extern "C" void kernel_launch(void* const* d_in, const int* in_sizes, int n_in,
                              void* d_out, int out_size) {
    const float* x = (const float*)d_in[0];
    float* out = (float*)d_out;

    init_minmax_kernel<<<1, 32>>>();

    edge_partial_kernel<<<dim3(HH/8, NSPLIT, BB), dim3(64, 4)>>>(x);

    edge_reduce_kernel<<<(BB*HW/4)/256, 256>>>();

    gauss_kernel<<<(BB*HW)/256, 256>>>();

    hblur_kernel<<<dim3(HH/4, CC/BCH, BB), dim3(64, 4)>>>(x);

    vblur_kernel<<<dim3(HH/4, CC/BCH, BB), dim3(64, 4)>>>(out);
}

// round 12
// speedup vs baseline: 1.1394x; 1.1213x over previous
#include <cuda_runtime.h>

#define BB 4
#define CC 64
#define HH 256
#define WW 256
#define HW (HH*WW)
#define CHW (CC*HW)

#define NSPLIT 8
#define ECH (CC/NSPLIT)   // 8 channels per edge block
#define SB 4              // channels staged per barrier pair in edge kernel
#define BCH 8             // channels per blur block

#define SIGMA_MIN 0.6f
#define SIGMA_MAX 1.2f

// Scratch (static device allocations — no cudaMalloc allowed)
__device__ float d_edge[BB*HW];                  // 1 MB
__device__ float d_edge_part[NSPLIT][BB*HW];     // 8 MB partial channel-sums
__device__ float d_g[4][BB*HW];                  // 4 MB (symmetric taps)
__device__ float d_tmp[(size_t)BB*CHW];          // 64 MB horizontal-pass result
__device__ unsigned int d_minmax[2*BB];          // per-batch {min,max} uint bits

__global__ void init_minmax_kernel() {
    int i = threadIdx.x;
    if (i < BB) {
        d_minmax[2*i]   = 0x7f800000u; // +inf
        d_minmax[2*i+1] = 0u;          // 0
    }
}

// Partial Sobel edge-energy sums over 8 channels per block.
// Block (64,4): 8-row x 256-col tile; 4 channels staged per barrier pair.
__global__ __launch_bounds__(256) void edge_partial_kernel(const float* __restrict__ x) {
    __shared__ float xs[SB][10][264];

    const int tx = threadIdx.x;
    const int ty = threadIdx.y;
    const int tid = ty*64 + tx;
    const int h0 = blockIdx.x*8;
    const int sp = blockIdx.y;
    const int b  = blockIdx.z;

    if (tid < SB*10) {
        int ch = tid / 10, r = tid % 10;
        xs[ch][r][3] = 0.f; xs[ch][r][260] = 0.f;
    }

    const float* xb = x + (size_t)b*CHW + (size_t)sp*ECH*HW;
    float acc[2][4] = {};

    for (int cb = 0; cb < ECH; cb += SB) {
        __syncthreads();
        #pragma unroll
        for (int k = 0; k < 10; k++) {
            int i  = tid + k*256;
            int ch = i / 640;
            int rm = i - ch*640;
            int r  = rm >> 6, q = rm & 63;
            int gh = h0 - 1 + r;
            float4 v = make_float4(0.f, 0.f, 0.f, 0.f);
            if (gh >= 0 && gh < HH)
                v = *(const float4*)(xb + (size_t)(cb + ch)*HW + gh*WW + q*4);
            *(float4*)&xs[ch][r][4 + q*4] = v;
        }
        __syncthreads();

        #pragma unroll
        for (int ch = 0; ch < SB; ch++) {
            #pragma unroll
            for (int rr = 0; rr < 2; rr++) {
                const int base = ty + rr*4;
                float d[3][4], s[3][4];
                #pragma unroll
                for (int r = 0; r < 3; r++) {
                    const float* row = &xs[ch][base + r][4 + 4*tx];
                    float  l = row[-1];
                    float4 m = *(const float4*)row;
                    float rt = row[4];
                    d[r][0] = m.y - l;    s[r][0] = l   + 2.f*m.x + m.y;
                    d[r][1] = m.z - m.x;  s[r][1] = m.x + 2.f*m.y + m.z;
                    d[r][2] = m.w - m.y;  s[r][2] = m.y + 2.f*m.z + m.w;
                    d[r][3] = rt  - m.z;  s[r][3] = m.z + 2.f*m.w + rt;
                }
                #pragma unroll
                for (int j = 0; j < 4; j++) {
                    float gx = d[0][j] + 2.f*d[1][j] + d[2][j];
                    float gy = s[2][j] - s[0][j];
                    acc[rr][j] = fmaf(gx, gx, acc[rr][j]);
                    acc[rr][j] = fmaf(gy, gy, acc[rr][j]);
                }
            }
        }
    }

    #pragma unroll
    for (int rr = 0; rr < 2; rr++) {
        const int h = h0 + ty + rr*4;
        float4 e = make_float4(acc[rr][0], acc[rr][1], acc[rr][2], acc[rr][3]);
        *(float4*)(d_edge_part[sp] + b*HW + h*WW + 4*tx) = e;
    }
}

// Sum partials -> edge; per-batch min/max via block reduce + uint atomics.
__global__ __launch_bounds__(256) void edge_reduce_kernel() {
    __shared__ float smin[8], smax[8];
    const int idx4 = blockIdx.x*256 + threadIdx.x;
    const int b = idx4 >> 14;

    float4 s = make_float4(0.f, 0.f, 0.f, 0.f);
    #pragma unroll
    for (int sp = 0; sp < NSPLIT; sp++) {
        float4 v = *(const float4*)(d_edge_part[sp] + (size_t)idx4*4);
        s.x += v.x; s.y += v.y; s.z += v.z; s.w += v.w;
    }
    s.x *= (1.f/64.f); s.y *= (1.f/64.f); s.z *= (1.f/64.f); s.w *= (1.f/64.f);
    *(float4*)(d_edge + (size_t)idx4*4) = s;

    float vmin = fminf(fminf(s.x, s.y), fminf(s.z, s.w));
    float vmax = fmaxf(fmaxf(s.x, s.y), fmaxf(s.z, s.w));
    #pragma unroll
    for (int o = 16; o; o >>= 1) {
        vmin = fminf(vmin, __shfl_xor_sync(0xffffffffu, vmin, o));
        vmax = fmaxf(vmax, __shfl_xor_sync(0xffffffffu, vmax, o));
    }
    const int wid = threadIdx.x >> 5, lane = threadIdx.x & 31;
    if (lane == 0) { smin[wid] = vmin; smax[wid] = vmax; }
    __syncthreads();
    if (threadIdx.x == 0) {
        float m = smin[0], M = smax[0];
        #pragma unroll
        for (int i = 1; i < 8; i++) { m = fminf(m, smin[i]); M = fmaxf(M, smax[i]); }
        atomicMin(&d_minmax[2*b],   __float_as_uint(m));
        atomicMax(&d_minmax[2*b+1], __float_as_uint(M));
    }
}

// Per-pixel normalized Gaussian taps. 1 expf per pixel; scalar = max parallelism.
__global__ __launch_bounds__(256) void gauss_kernel() {
    const int idx = blockIdx.x*256 + threadIdx.x;
    const int b = idx >> 16;   // HW per batch
    const float emin = __uint_as_float(d_minmax[2*b]);
    const float rden = __fdividef(1.f, __uint_as_float(d_minmax[2*b+1]) + 1e-6f);

    float e = (d_edge[idx] - emin) * rden;
    float s = SIGMA_MIN + (SIGMA_MAX - SIGMA_MIN)*e;
    float t = __fdividef(1.f, s);
    float inv = 0.5f*t*t;
    float w2 = __expf(-inv);
    float w2_2 = w2*w2;
    float w1 = w2_2*w2_2;
    float w0 = w1*w1*w2;
    float r = __fdividef(1.f, 2.f*(w0 + w1 + w2) + 1.f);
    d_g[0][idx] = w0*r;
    d_g[1][idx] = w1*r;
    d_g[2][idx] = w2*r;
    d_g[3][idx] = r;
}

// Horizontal pass: thread = 4 outputs x 8 channels; g in regs; no barriers.
__global__ __launch_bounds__(256) void hblur_kernel(const float* __restrict__ x) {
    const int tx = threadIdx.x;                 // 0..63
    const int h  = blockIdx.x*4 + threadIdx.y;
    const int c0 = blockIdx.y*BCH;
    const int b  = blockIdx.z;
    const int w4 = tx*4;
    const int pidx = b*HW + h*WW + w4;

    const float4 G0 = *(const float4*)&d_g[0][pidx];
    const float4 G1 = *(const float4*)&d_g[1][pidx];
    const float4 G2 = *(const float4*)&d_g[2][pidx];
    const float4 G3 = *(const float4*)&d_g[3][pidx];

    const float* xr = x     + (size_t)b*CHW + (size_t)c0*HW + h*WW + w4;
    float*       tr = d_tmp + (size_t)b*CHW + (size_t)c0*HW + h*WW + w4;
    const bool hasL = (tx > 0), hasR = (tx < 63);
    const float4 z4 = make_float4(0.f, 0.f, 0.f, 0.f);

    #pragma unroll 2
    for (int c = 0; c < BCH; c++) {
        const float* p = xr + (size_t)c*HW;
        float4 m  = *(const float4*)p;
        float4 lf = hasL ? *(const float4*)(p - 4) : z4;
        float4 rf = hasR ? *(const float4*)(p + 4) : z4;
        float v0=lf.y, v1=lf.z, v2=lf.w, v3=m.x, v4=m.y, v5=m.z, v6=m.w, v7=rf.x, v8=rf.y, v9=rf.z;
        float4 o;
        o.x = fmaf(G0.x, v0+v6, fmaf(G1.x, v1+v5, fmaf(G2.x, v2+v4, G3.x*v3)));
        o.y = fmaf(G0.y, v1+v7, fmaf(G1.y, v2+v6, fmaf(G2.y, v3+v5, G3.y*v4)));
        o.z = fmaf(G0.z, v2+v8, fmaf(G1.z, v3+v7, fmaf(G2.z, v4+v6, G3.z*v5)));
        o.w = fmaf(G0.w, v3+v9, fmaf(G1.w, v4+v8, fmaf(G2.w, v5+v7, G3.w*v6)));
        *(float4*)(tr + (size_t)c*HW) = o;
    }
}

// Vertical pass v2: thread = 4 consecutive output rows x 8 channels.
// Per channel: 10-row register window (10 LDG.128) -> 4 outputs (4 STG.128).
// LDG per output drops 7 -> 2.5; MLP=10 covers DRAM latency.
__global__ __launch_bounds__(256) void vblur_kernel(float* __restrict__ out) {
    const int tx = threadIdx.x;                      // 0..63 (column quad)
    const int ty = threadIdx.y;                      // 0..3 (4-row group)
    const int h0 = blockIdx.x*16 + ty*4;             // first output row
    const int c0 = blockIdx.y*BCH;
    const int b  = blockIdx.z;
    const int w4 = tx*4;

    // per-row g for this thread's 4 output rows (reused across 8 channels)
    float4 G0[4], G1[4], G2[4], G3[4];
    #pragma unroll
    for (int j = 0; j < 4; j++) {
        const int gi = b*HW + (h0 + j)*WW + w4;
        G0[j] = *(const float4*)&d_g[0][gi];
        G1[j] = *(const float4*)&d_g[1][gi];
        G2[j] = *(const float4*)&d_g[2][gi];
        G3[j] = *(const float4*)&d_g[3][gi];
    }

    const float* tp = d_tmp + (size_t)b*CHW + (size_t)c0*HW + w4;
    float*       op = out   + (size_t)b*CHW + (size_t)c0*HW + w4;
    const float4 z4 = make_float4(0.f, 0.f, 0.f, 0.f);
    const bool interior = (h0 >= 3) && (h0 + 6 < HH);

    if (interior) {
        for (int c = 0; c < BCH; c++) {
            const float* p = tp + (size_t)c*HW + (h0 - 3)*WW;
            float4 wn[10];
            #pragma unroll
            for (int i = 0; i < 10; i++)
                wn[i] = *(const float4*)(p + i*WW);
            float* o = op + (size_t)c*HW + h0*WW;
            #pragma unroll
            for (int j = 0; j < 4; j++) {
                float4 v;
                v.x = fmaf(G0[j].x, wn[j].x+wn[j+6].x, fmaf(G1[j].x, wn[j+1].x+wn[j+5].x, fmaf(G2[j].x, wn[j+2].x+wn[j+4].x, G3[j].x*wn[j+3].x)));
                v.y = fmaf(G0[j].y, wn[j].y+wn[j+6].y, fmaf(G1[j].y, wn[j+1].y+wn[j+5].y, fmaf(G2[j].y, wn[j+2].y+wn[j+4].y, G3[j].y*wn[j+3].y)));
                v.z = fmaf(G0[j].z, wn[j].z+wn[j+6].z, fmaf(G1[j].z, wn[j+1].z+wn[j+5].z, fmaf(G2[j].z, wn[j+2].z+wn[j+4].z, G3[j].z*wn[j+3].z)));
                v.w = fmaf(G0[j].w, wn[j].w+wn[j+6].w, fmaf(G1[j].w, wn[j+1].w+wn[j+5].w, fmaf(G2[j].w, wn[j+2].w+wn[j+4].w, G3[j].w*wn[j+3].w)));
                *(float4*)(o + j*WW) = v;
            }
        }
    } else {
        bool ok[10];
        #pragma unroll
        for (int i = 0; i < 10; i++) {
            int r = h0 - 3 + i;
            ok[i] = (r >= 0) && (r < HH);
        }
        for (int c = 0; c < BCH; c++) {
            const float* p = tp + (size_t)c*HW + (h0 - 3)*WW;
            float4 wn[10];
            #pragma unroll
            for (int i = 0; i < 10; i++)
                wn[i] = ok[i] ? *(const float4*)(p + i*WW) : z4;
            float* o = op + (size_t)c*HW + h0*WW;
            #pragma unroll
            for (int j = 0; j < 4; j++) {
                float4 v;
                v.x = fmaf(G0[j].x, wn[j].x+wn[j+6].x, fmaf(G1[j].x, wn[j+1].x+wn[j+5].x, fmaf(G2[j].x, wn[j+2].x+wn[j+4].x, G3[j].x*wn[j+3].x)));
                v.y = fmaf(G0[j].y, wn[j].y+wn[j+6].y, fmaf(G1[j].y, wn[j+1].y+wn[j+5].y, fmaf(G2[j].y, wn[j+2].y+wn[j+4].y, G3[j].y*wn[j+3].y)));
                v.z = fmaf(G0[j].z, wn[j].z+wn[j+6].z, fmaf(G1[j].z, wn[j+1].z+wn[j+5].z, fmaf(G2[j].z, wn[j+2].z+wn[j+4].z, G3[j].z*wn[j+3].z)));
                v.w = fmaf(G0[j].w, wn[j].w+wn[j+6].w, fmaf(G1[j].w, wn[j+1].w+wn[j+5].w, fmaf(G2[j].w, wn[j+2].w+wn[j+4].w, G3[j].w*wn[j+3].w)));
                *(float4*)(o + j*WW) = v;
            }
        }
    }
}

extern "C" void kernel_launch(void* const* d_in, const int* in_sizes, int n_in,
                              void* d_out, int out_size) {
    const float* x = (const float*)d_in[0];
    float* out = (float*)d_out;

    init_minmax_kernel<<<1, 32>>>();

    edge_partial_kernel<<<dim3(HH/8, NSPLIT, BB), dim3(64, 4)>>>(x);

    edge_reduce_kernel<<<(BB*HW/4)/256, 256>>>();

    gauss_kernel<<<(BB*HW)/256, 256>>>();

    hblur_kernel<<<dim3(HH/4, CC/BCH, BB), dim3(64, 4)>>>(x);

    vblur_kernel<<<dim3(HH/16, CC/BCH, BB), dim3(64, 4)>>>(out);
}